// round 2
// baseline (speedup 1.0000x reference)
#include <cuda_runtime.h>
#include <math.h>

#define BB 32
#define TT 512
#define HH 512
#define G4 2048

// ---------------- device scratch (static; no dynamic allocation) ----------------
__device__ float    g_xg[(size_t)2 * TT * BB * G4];     // [dir][t][b][4H]  268 MB
__device__ float    g_hbuf[2 * 2 * BB * HH];            // [dir][ping][b][h]
__device__ unsigned g_bar[2 * TT];                      // per-dir per-step arrival counters

// ---------------- kernel 1: input projection GEMM ----------------
// out[m][n] = sum_k x[m][k] * W[n][k] + b_ih[n] + b_hh[n]
// M = 16384 (m = b*512 + t), N = 4096 (dir*2048 + g), K = 512
__global__ __launch_bounds__(256)
void gemm_xg_kernel(const float* __restrict__ x,
                    const float* __restrict__ Wf, const float* __restrict__ Wb,
                    const float* __restrict__ bif, const float* __restrict__ bhf,
                    const float* __restrict__ bib, const float* __restrict__ bhb)
{
    __shared__ float As[8][132];
    __shared__ float Bs[8][132];
    const int tid   = threadIdx.x;
    const int ntile = blockIdx.x << 7;          // 0..4095 step 128 (never straddles dir)
    const int mtile = blockIdx.y << 7;
    const int dir   = ntile >> 11;
    const int nloc  = ntile & 2047;
    const float* __restrict__ W = dir ? Wb : Wf;

    const int lrow = tid >> 1;                  // 0..127
    const int lk   = (tid & 1) << 2;            // 0 or 4

    const float* aG = x + (size_t)(mtile + lrow) * 512 + lk;
    const float* bG = W + (size_t)(nloc  + lrow) * 512 + lk;

    float acc[8][8];
#pragma unroll
    for (int i = 0; i < 8; ++i)
#pragma unroll
        for (int j = 0; j < 8; ++j) acc[i][j] = 0.f;

    const int tm = tid & 15;
    const int tn = tid >> 4;

    float4 av = *(const float4*)aG;
    float4 bv = *(const float4*)bG;

    for (int kt = 0; kt < 64; ++kt) {
        As[lk+0][lrow] = av.x; As[lk+1][lrow] = av.y;
        As[lk+2][lrow] = av.z; As[lk+3][lrow] = av.w;
        Bs[lk+0][lrow] = bv.x; Bs[lk+1][lrow] = bv.y;
        Bs[lk+2][lrow] = bv.z; Bs[lk+3][lrow] = bv.w;
        __syncthreads();
        if (kt < 63) {
            av = *(const float4*)(aG + (kt + 1) * 8);
            bv = *(const float4*)(bG + (kt + 1) * 8);
        }
#pragma unroll
        for (int kk = 0; kk < 8; ++kk) {
            float4 a0 = *(const float4*)&As[kk][tm * 4];
            float4 a1 = *(const float4*)&As[kk][tm * 4 + 64];
            float4 b0 = *(const float4*)&Bs[kk][tn * 4];
            float4 b1 = *(const float4*)&Bs[kk][tn * 4 + 64];
            float am[8] = {a0.x, a0.y, a0.z, a0.w, a1.x, a1.y, a1.z, a1.w};
            float bn[8] = {b0.x, b0.y, b0.z, b0.w, b1.x, b1.y, b1.z, b1.w};
#pragma unroll
            for (int i = 0; i < 8; ++i)
#pragma unroll
                for (int j = 0; j < 8; ++j)
                    acc[i][j] = fmaf(am[i], bn[j], acc[i][j]);
        }
        __syncthreads();
    }

    const float* bi = dir ? bib : bif;
    const float* bh = dir ? bhb : bhf;
    const int g0 = nloc + tn * 4;
    const int g1 = g0 + 64;
    float bs0[4], bs1[4];
#pragma unroll
    for (int j = 0; j < 4; ++j) { bs0[j] = bi[g0+j] + bh[g0+j]; bs1[j] = bi[g1+j] + bh[g1+j]; }

#pragma unroll
    for (int i = 0; i < 8; ++i) {
        int mi = (i < 4) ? (tm * 4 + i) : (64 + tm * 4 + (i - 4));
        int m  = mtile + mi;
        int b  = m >> 9;
        int t  = m & 511;
        float* orow = g_xg + (((size_t)dir * TT + t) * BB + b) * G4;
        float4 o0, o1;
        o0.x = acc[i][0] + bs0[0]; o0.y = acc[i][1] + bs0[1];
        o0.z = acc[i][2] + bs0[2]; o0.w = acc[i][3] + bs0[3];
        o1.x = acc[i][4] + bs1[0]; o1.y = acc[i][5] + bs1[1];
        o1.z = acc[i][6] + bs1[2]; o1.w = acc[i][7] + bs1[3];
        *(float4*)&orow[g0] = o0;
        *(float4*)&orow[g1] = o1;
    }
}

// ---------------- kernel 2: persistent recurrent scan ----------------
// 128 CTAs (64/dir), 128 threads. CTA owns h columns [jbase, jbase+8) for all 32
// batches (c-state in smem for all 512 steps). Per-step cross-CTA dependency on
// full h handled by per-direction atomic arrival counters (all CTAs co-resident).
#define SCAN_SMEM_BYTES ((32*516 + 32*8*4 + 32*8 + 32) * 4)

__global__ __launch_bounds__(128, 1)
void lstm_scan_kernel(const int* __restrict__ lengths,
                      const float* __restrict__ Whhf,
                      const float* __restrict__ Whhb,
                      float* __restrict__ out)
{
    extern __shared__ float sm[];
    float* sh_h = sm;                         // [32][516] padded h_prev
    float* sh_g = sm + 32 * 516;              // [32][8][4] gates
    float* sh_c = sh_g + 32 * 8 * 4;          // [32][8] cell state
    int*   sh_len = (int*)(sh_c + 32 * 8);    // [32]

    const int tid   = threadIdx.x;
    const int d     = blockIdx.x >> 6;
    const int cta   = blockIdx.x & 63;
    const int jbase = cta << 3;
    const float* __restrict__ Wd = d ? Whhb : Whhf;

    if (tid < 32) sh_len[tid] = lengths[tid];
    sh_c[tid] = 0.f; sh_c[tid + 128] = 0.f;

    // gate-compute mapping: thread -> (jj 0..7, gate-pair gp, 4-batch group b0)
    const int jj  = tid & 7;
    const int gp  = (tid >> 3) & 1;
    const int b0  = (tid >> 4) << 2;
    const int col = jbase + jj;
    const float* __restrict__ w0 = Wd + ((size_t)(gp * 2 + 0) * 512 + col) * 512;
    const float* __restrict__ w1 = Wd + ((size_t)(gp * 2 + 1) * 512 + col) * 512;

    unsigned* bar = g_bar  + d * TT;
    float*    hb  = g_hbuf + (size_t)d * 2 * BB * HH;
    const int cell0 = tid * 2;

    for (int s = 0; s < TT; ++s) {
        const int tt = d ? (511 - s) : s;
        const int p  = s & 1;

        // stage h_prev (L2-coherent loads; L1 may be stale across SMs)
        const float* hsrc = hb + p * BB * HH;
        for (int i = tid; i < (BB * HH) / 4; i += 128) {
            int fl = i << 2;
            int b  = fl >> 9, k = fl & 511;
            float4 v = __ldcg((const float4*)(hsrc + fl));
            *(float4*)&sh_h[b * 516 + k] = v;
        }
        __syncthreads();

        // gate accumulation: init from xg, then += h @ W_hh^T
        const float* xgb = g_xg + (((size_t)d * TT + tt) * BB) * G4;
        float acc[4][2];
#pragma unroll
        for (int bb = 0; bb < 4; ++bb) {
            const float* xr = xgb + (size_t)(b0 + bb) * G4 + col;
            acc[bb][0] = __ldg(xr + (gp * 2 + 0) * 512);
            acc[bb][1] = __ldg(xr + (gp * 2 + 1) * 512);
        }
#pragma unroll 2
        for (int kq = 0; kq < 128; ++kq) {
            float4 wa = *(const float4*)(w0 + kq * 4);
            float4 wb = *(const float4*)(w1 + kq * 4);
#pragma unroll
            for (int bb = 0; bb < 4; ++bb) {
                float4 hv = *(const float4*)&sh_h[(b0 + bb) * 516 + kq * 4];
                acc[bb][0] = fmaf(hv.x, wa.x, acc[bb][0]);
                acc[bb][0] = fmaf(hv.y, wa.y, acc[bb][0]);
                acc[bb][0] = fmaf(hv.z, wa.z, acc[bb][0]);
                acc[bb][0] = fmaf(hv.w, wa.w, acc[bb][0]);
                acc[bb][1] = fmaf(hv.x, wb.x, acc[bb][1]);
                acc[bb][1] = fmaf(hv.y, wb.y, acc[bb][1]);
                acc[bb][1] = fmaf(hv.z, wb.z, acc[bb][1]);
                acc[bb][1] = fmaf(hv.w, wb.w, acc[bb][1]);
            }
        }
#pragma unroll
        for (int bb = 0; bb < 4; ++bb) {
            sh_g[((b0 + bb) * 8 + jj) * 4 + gp * 2 + 0] = acc[bb][0];
            sh_g[((b0 + bb) * 8 + jj) * 4 + gp * 2 + 1] = acc[bb][1];
        }
        __syncthreads();

        // cell update: 2 (b,j) cells per thread
        float* hnext = hb + (p ^ 1) * BB * HH;
#pragma unroll
        for (int u = 0; u < 2; ++u) {
            int cell = cell0 + u;
            int b = cell >> 3, j = cell & 7;
            int hc = jbase + j;
            float4 gv = *(float4*)&sh_g[cell * 4];
            float ig = 1.f / (1.f + expf(-gv.x));
            float fg = 1.f / (1.f + expf(-gv.y));
            float gg = tanhf(gv.z);
            float og = 1.f / (1.f + expf(-gv.w));
            float c  = sh_c[cell];
            float cn = fg * c + ig * gg;
            float hn = og * tanhf(cn);
            float h;
            if (tt < sh_len[b]) { c = cn; h = hn; }
            else                { h = sh_h[b * 516 + hc]; }
            sh_c[cell] = c;
            __stcg(hnext + b * HH + hc, h);
            out[((size_t)(b * TT + tt)) * 1024 + d * HH + hc] = h;
        }

        // cross-CTA barrier (per direction, 64 arrivals)
        __threadfence();
        __syncthreads();
        if (tid == 0) {
            atomicAdd(&bar[s], 1u);
            while (*((volatile unsigned*)&bar[s]) < 64u) { __nanosleep(64); }
        }
        __syncthreads();
        __threadfence();
    }
}

extern "C" void kernel_launch(void* const* d_in, const int* in_sizes, int n_in,
                              void* d_out, int out_size)
{
    const float* x    = (const float*)d_in[0];
    const int*   len  = (const int*)  d_in[1];
    const float* Wihf = (const float*)d_in[2];
    const float* Whhf = (const float*)d_in[3];
    const float* bihf = (const float*)d_in[4];
    const float* bhhf = (const float*)d_in[5];
    const float* Wihb = (const float*)d_in[6];
    const float* Whhb = (const float*)d_in[7];
    const float* bihb = (const float*)d_in[8];
    const float* bhhb = (const float*)d_in[9];
    float* out = (float*)d_out;

    void* barp = 0; void* hbp = 0;
    cudaGetSymbolAddress(&barp, g_bar);
    cudaGetSymbolAddress(&hbp,  g_hbuf);
    cudaMemsetAsync(barp, 0, 2 * TT * sizeof(unsigned));
    cudaMemsetAsync(hbp,  0, (size_t)2 * 2 * BB * HH * sizeof(float));

    dim3 ggrid(32, 128);
    gemm_xg_kernel<<<ggrid, 256>>>(x, Wihf, Wihb, bihf, bhhf, bihb, bhhb);

    cudaFuncSetAttribute(lstm_scan_kernel,
                         cudaFuncAttributeMaxDynamicSharedMemorySize, SCAN_SMEM_BYTES);
    lstm_scan_kernel<<<128, 128, SCAN_SMEM_BYTES>>>(len, Whhf, Whhb, out);
}

// round 3
// speedup vs baseline: 2.4820x; 2.4820x over previous
#include <cuda_runtime.h>
#include <math.h>

#define BB 32
#define TT 512
#define HH 512
#define G4 2048

// ---------------- device scratch (static; no dynamic allocation) ----------------
__device__ float    g_xg[(size_t)2 * TT * BB * G4];     // [dir][t][b][4H]  268 MB
__device__ float    g_hbuf[2 * 2 * BB * HH];            // [dir][ping][b][h]
__device__ unsigned g_bar[2 * TT];                      // per-dir per-step arrival counters

// ---------------- kernel 1: input projection GEMM (unchanged from R2) ----------------
__global__ __launch_bounds__(256)
void gemm_xg_kernel(const float* __restrict__ x,
                    const float* __restrict__ Wf, const float* __restrict__ Wb,
                    const float* __restrict__ bif, const float* __restrict__ bhf,
                    const float* __restrict__ bib, const float* __restrict__ bhb)
{
    __shared__ float As[8][132];
    __shared__ float Bs[8][132];
    const int tid   = threadIdx.x;
    const int ntile = blockIdx.x << 7;
    const int mtile = blockIdx.y << 7;
    const int dir   = ntile >> 11;
    const int nloc  = ntile & 2047;
    const float* __restrict__ W = dir ? Wb : Wf;

    const int lrow = tid >> 1;
    const int lk   = (tid & 1) << 2;

    const float* aG = x + (size_t)(mtile + lrow) * 512 + lk;
    const float* bG = W + (size_t)(nloc  + lrow) * 512 + lk;

    float acc[8][8];
#pragma unroll
    for (int i = 0; i < 8; ++i)
#pragma unroll
        for (int j = 0; j < 8; ++j) acc[i][j] = 0.f;

    const int tm = tid & 15;
    const int tn = tid >> 4;

    float4 av = *(const float4*)aG;
    float4 bv = *(const float4*)bG;

    for (int kt = 0; kt < 64; ++kt) {
        As[lk+0][lrow] = av.x; As[lk+1][lrow] = av.y;
        As[lk+2][lrow] = av.z; As[lk+3][lrow] = av.w;
        Bs[lk+0][lrow] = bv.x; Bs[lk+1][lrow] = bv.y;
        Bs[lk+2][lrow] = bv.z; Bs[lk+3][lrow] = bv.w;
        __syncthreads();
        if (kt < 63) {
            av = *(const float4*)(aG + (kt + 1) * 8);
            bv = *(const float4*)(bG + (kt + 1) * 8);
        }
#pragma unroll
        for (int kk = 0; kk < 8; ++kk) {
            float4 a0 = *(const float4*)&As[kk][tm * 4];
            float4 a1 = *(const float4*)&As[kk][tm * 4 + 64];
            float4 b0 = *(const float4*)&Bs[kk][tn * 4];
            float4 b1 = *(const float4*)&Bs[kk][tn * 4 + 64];
            float am[8] = {a0.x, a0.y, a0.z, a0.w, a1.x, a1.y, a1.z, a1.w};
            float bn[8] = {b0.x, b0.y, b0.z, b0.w, b1.x, b1.y, b1.z, b1.w};
#pragma unroll
            for (int i = 0; i < 8; ++i)
#pragma unroll
                for (int j = 0; j < 8; ++j)
                    acc[i][j] = fmaf(am[i], bn[j], acc[i][j]);
        }
        __syncthreads();
    }

    const float* bi = dir ? bib : bif;
    const float* bh = dir ? bhb : bhf;
    const int g0 = nloc + tn * 4;
    const int g1 = g0 + 64;
    float bs0[4], bs1[4];
#pragma unroll
    for (int j = 0; j < 4; ++j) { bs0[j] = bi[g0+j] + bh[g0+j]; bs1[j] = bi[g1+j] + bh[g1+j]; }

#pragma unroll
    for (int i = 0; i < 8; ++i) {
        int mi = (i < 4) ? (tm * 4 + i) : (64 + tm * 4 + (i - 4));
        int m  = mtile + mi;
        int b  = m >> 9;
        int t  = m & 511;
        float* orow = g_xg + (((size_t)dir * TT + t) * BB + b) * G4;
        float4 o0, o1;
        o0.x = acc[i][0] + bs0[0]; o0.y = acc[i][1] + bs0[1];
        o0.z = acc[i][2] + bs0[2]; o0.w = acc[i][3] + bs0[3];
        o1.x = acc[i][4] + bs1[0]; o1.y = acc[i][5] + bs1[1];
        o1.z = acc[i][6] + bs1[2]; o1.w = acc[i][7] + bs1[3];
        *(float4*)&orow[g0] = o0;
        *(float4*)&orow[g1] = o1;
    }
}

// ---------------- kernel 2: persistent recurrent scan (reworked) ----------------
// 128 CTAs (64/dir), 256 threads, 1 CTA/SM. CTA owns 8 h-columns for all 32 batches.
// W_hh rows for those columns (32 rows x 512) live in SMEM for the entire scan,
// killing the 16-lines-per-LDG L1 wavefront storm seen in R2. h_prev staged per
// step via __ldcg (L2-coherent). Per-dir atomic arrival barrier (all co-resident).
//
// smem: sh_h [32][516] + sh_w [32][516] + sh_g [256][4] + sh_c [256] + len [32]
#define SCAN_SMEM_FLOATS (32*516 + 32*516 + 256*4 + 256 + 32)
#define SCAN_SMEM_BYTES  (SCAN_SMEM_FLOATS * 4)

__global__ __launch_bounds__(256, 1)
void lstm_scan_kernel(const int* __restrict__ lengths,
                      const float* __restrict__ Whhf,
                      const float* __restrict__ Whhb,
                      float* __restrict__ out)
{
    extern __shared__ float sm[];
    float* sh_h = sm;                           // [32][516] padded h_prev
    float* sh_w = sm + 32 * 516;                // [32][516]: row r=(gate*8+jj), k padded
    float* sh_g = sh_w + 32 * 516;              // [256][4] gates per cell
    float* sh_c = sh_g + 256 * 4;               // [256] cell state
    int*   sh_len = (int*)(sh_c + 256);         // [32]

    const int tid   = threadIdx.x;
    const int d     = blockIdx.x >> 6;
    const int cta   = blockIdx.x & 63;
    const int jbase = cta << 3;
    const float* __restrict__ Wd = d ? Whhb : Whhf;

    if (tid < 32) sh_len[tid] = lengths[tid];
    sh_c[tid] = 0.f;

    // preload W_hh rows (gate 0..3, col jbase..jbase+7) -> sh_w[gate*8+jj][k]
    for (int i = tid; i < (32 * 512) / 4; i += 256) {
        int flat = i << 2;
        int r = flat >> 9;              // 0..31
        int k = flat & 511;
        int gate = r >> 3, jj = r & 7;
        float4 v = *(const float4*)(Wd + ((size_t)(gate * 512 + jbase + jj)) * 512 + k);
        *(float4*)&sh_w[r * 516 + k] = v;
    }

    // thread mapping for gate compute: jj 0..7, gate-pair gp 0..1, batch pair b0
    const int jj  = tid & 7;
    const int gp  = (tid >> 3) & 1;
    const int b0  = (tid >> 4) << 1;    // 0,2,..,30
    const int col = jbase + jj;
    const float* wrow0 = &sh_w[((gp * 2 + 0) * 8 + jj) * 516];
    const float* wrow1 = &sh_w[((gp * 2 + 1) * 8 + jj) * 516];

    unsigned* bar = g_bar  + d * TT;
    float*    hb  = g_hbuf + (size_t)d * 2 * BB * HH;

    // cell-update mapping: 1 cell per thread
    const int cb = tid >> 3;            // batch 0..31
    const int cj = tid & 7;             // col offset 0..7
    const int hc = jbase + cj;

    __syncthreads();

    for (int s = 0; s < TT; ++s) {
        const int tt = d ? (511 - s) : s;
        const int p  = s & 1;

        // issue xg loads first (independent of barrier/staging) to overlap latency
        const float* xgb = g_xg + (((size_t)d * TT + tt) * BB) * G4;
        float a00 = __ldg(xgb + (size_t)(b0 + 0) * G4 + (gp * 2 + 0) * 512 + col);
        float a01 = __ldg(xgb + (size_t)(b0 + 0) * G4 + (gp * 2 + 1) * 512 + col);
        float a10 = __ldg(xgb + (size_t)(b0 + 1) * G4 + (gp * 2 + 0) * 512 + col);
        float a11 = __ldg(xgb + (size_t)(b0 + 1) * G4 + (gp * 2 + 1) * 512 + col);

        // stage h_prev (L2-coherent loads; L1 may be stale across SMs)
        const float* hsrc = hb + p * BB * HH;
        for (int i = tid; i < (BB * HH) / 4; i += 256) {
            int fl = i << 2;
            int b  = fl >> 9, k = fl & 511;
            float4 v = __ldcg((const float4*)(hsrc + fl));
            *(float4*)&sh_h[b * 516 + k] = v;
        }
        __syncthreads();

        // gates += h @ W_hh^T   (all operands in smem)
#pragma unroll 4
        for (int kq = 0; kq < 128; ++kq) {
            float4 wa = *(const float4*)(wrow0 + kq * 4);
            float4 wb = *(const float4*)(wrow1 + kq * 4);
            float4 h0 = *(const float4*)&sh_h[(b0 + 0) * 516 + kq * 4];
            float4 h1 = *(const float4*)&sh_h[(b0 + 1) * 516 + kq * 4];
            a00 = fmaf(h0.x, wa.x, a00); a00 = fmaf(h0.y, wa.y, a00);
            a00 = fmaf(h0.z, wa.z, a00); a00 = fmaf(h0.w, wa.w, a00);
            a01 = fmaf(h0.x, wb.x, a01); a01 = fmaf(h0.y, wb.y, a01);
            a01 = fmaf(h0.z, wb.z, a01); a01 = fmaf(h0.w, wb.w, a01);
            a10 = fmaf(h1.x, wa.x, a10); a10 = fmaf(h1.y, wa.y, a10);
            a10 = fmaf(h1.z, wa.z, a10); a10 = fmaf(h1.w, wa.w, a10);
            a11 = fmaf(h1.x, wb.x, a11); a11 = fmaf(h1.y, wb.y, a11);
            a11 = fmaf(h1.z, wb.z, a11); a11 = fmaf(h1.w, wb.w, a11);
        }
        sh_g[((b0 + 0) * 8 + jj) * 4 + gp * 2 + 0] = a00;
        sh_g[((b0 + 0) * 8 + jj) * 4 + gp * 2 + 1] = a01;
        sh_g[((b0 + 1) * 8 + jj) * 4 + gp * 2 + 0] = a10;
        sh_g[((b0 + 1) * 8 + jj) * 4 + gp * 2 + 1] = a11;
        __syncthreads();

        // cell update: one (b, j) cell per thread
        float* hnext = hb + (p ^ 1) * BB * HH;
        {
            float4 gv = *(float4*)&sh_g[tid * 4];
            float ig = 1.f / (1.f + expf(-gv.x));
            float fg = 1.f / (1.f + expf(-gv.y));
            float gg = tanhf(gv.z);
            float og = 1.f / (1.f + expf(-gv.w));
            float c  = sh_c[tid];
            float cn = fg * c + ig * gg;
            float hn = og * tanhf(cn);
            float h;
            if (tt < sh_len[cb]) { c = cn; h = hn; }
            else                 { h = sh_h[cb * 516 + hc]; }
            sh_c[tid] = c;
            __stcg(hnext + cb * HH + hc, h);
            out[((size_t)(cb * TT + tt)) * 1024 + d * HH + hc] = h;
        }

        // cross-CTA barrier (per direction, 64 arrivals); single-thread fences
        __syncthreads();
        if (s < TT - 1 && tid == 0) {
            __threadfence();                       // release: order h stores before counter
            atomicAdd(&bar[s], 1u);
            while (*((volatile unsigned*)&bar[s]) < 64u) { __nanosleep(32); }
            __threadfence();                       // acquire: order counter before h reads
        }
        __syncthreads();
    }
}

extern "C" void kernel_launch(void* const* d_in, const int* in_sizes, int n_in,
                              void* d_out, int out_size)
{
    const float* x    = (const float*)d_in[0];
    const int*   len  = (const int*)  d_in[1];
    const float* Wihf = (const float*)d_in[2];
    const float* Whhf = (const float*)d_in[3];
    const float* bihf = (const float*)d_in[4];
    const float* bhhf = (const float*)d_in[5];
    const float* Wihb = (const float*)d_in[6];
    const float* Whhb = (const float*)d_in[7];
    const float* bihb = (const float*)d_in[8];
    const float* bhhb = (const float*)d_in[9];
    float* out = (float*)d_out;

    void* barp = 0; void* hbp = 0;
    cudaGetSymbolAddress(&barp, g_bar);
    cudaGetSymbolAddress(&hbp,  g_hbuf);
    cudaMemsetAsync(barp, 0, 2 * TT * sizeof(unsigned));
    cudaMemsetAsync(hbp,  0, (size_t)2 * 2 * BB * HH * sizeof(float));

    dim3 ggrid(32, 128);
    gemm_xg_kernel<<<ggrid, 256>>>(x, Wihf, Wihb, bihf, bhhf, bihb, bhhb);

    cudaFuncSetAttribute(lstm_scan_kernel,
                         cudaFuncAttributeMaxDynamicSharedMemorySize, SCAN_SMEM_BYTES);
    lstm_scan_kernel<<<128, 256, SCAN_SMEM_BYTES>>>(len, Whhf, Whhb, out);
}